// round 7
// baseline (speedup 1.0000x reference)
#include <cuda_runtime.h>

#define MARGIN  1.9f
#define GRID    592              // 4 blocks/SM on 148 SMs, all wave-1 resident
#define NMAXE   1024
#define BSCALE  8.0f             // 256 buckets over d in [0,32)

// Scratch (no allocation allowed)
__device__ float g_dot[640 * 640];   // full dot products
__device__ float g_sq[NMAXE];
__device__ int   g_lab[NMAXE];
__device__ float g_bsum[GRID];
__device__ int   g_bcnt[GRID];
__device__ int   g_bval[GRID];
__device__ int   g_bar1 = 0;
__device__ int   g_bar2 = 0;

// Fused kernel, grid=592:
//  phase 1: blocks 0..99  : 64x64 full-k dot tiles (4x4 micro, float4 operand
//                           reads, k as 2 sequential 64-chunks) -> one SM each
//           blocks 100..119: 32 row sq-norms each
//           block  120     : label normalization; 121..591 idle
//  grid barrier
//  phase 2: block b -> anchors i = b, b+592. Counting-sort histogram of
//           negatives, prefix scans, O(1)+boundary query per positive.
//  phase 3: last block reduces partials -> out[4], resets barriers
__global__ void __launch_bounds__(256, 4)
fused_triplet_kernel(const float* __restrict__ e, const int* __restrict__ lab32,
                     float* __restrict__ out, int n) {
    __shared__ float As[64 * 68];    // 17.4 KB (phase 1, row-major k-contiguous)
    __shared__ float Bs[64 * 64];    // 16 KB   (phase 1, k-major)
    __shared__ int   hcnt[256];
    __shared__ int   pcs[257];
    __shared__ int   cur[256];
    __shared__ float pvs[256];
    __shared__ float bval[704];
    __shared__ int   swi[8], swi2[8];
    __shared__ float swf[8], swf2[8];
    __shared__ int   s_old, s_is64;
    __shared__ float wsum[8];
    __shared__ int   wcnt[8];

    const int b    = blockIdx.x;
    const int tid  = threadIdx.x;
    const int lane = tid & 31;
    const int wid  = tid >> 5;
    const float4* e4 = (const float4*)e;

    const int tiles_x     = n >> 6;                    // 10
    const int dist_blocks = tiles_x * tiles_x;         // 100
    const int sq_blocks   = n >> 5;                    // 20
    const int lab_block   = dist_blocks + sq_blocks;   // 120

    // ================= phase 1 =================
    if (b < dist_blocks) {
        const int ti = b / tiles_x;
        const int tj = b % tiles_x;
        const int tx = tid & 15;
        const int ty = tid >> 4;

        float acc[4][4];
        #pragma unroll
        for (int q = 0; q < 4; q++)
            #pragma unroll
            for (int r = 0; r < 4; r++) acc[q][r] = 0.f;

        #pragma unroll
        for (int ch = 0; ch < 2; ch++) {
            __syncthreads();
            // A chunk [64][64] row-major (stride 68), coalesced LDG.128
            #pragma unroll
            for (int r = 0; r < 4; r++) {
                int lin = tid + r * 256;
                int row = lin >> 4;
                int c4  = lin & 15;
                float4 v = e4[(size_t)(ti * 64 + row) * 32 + ch * 16 + c4];
                *(float4*)&As[row * 68 + c4 * 4] = v;
            }
            // B chunk k-major [64][64]
            #pragma unroll
            for (int r = 0; r < 4; r++) {
                int lin = tid + r * 256;
                int j   = lin & 63;
                int c4i = lin >> 6;
                float4 v = e4[(size_t)(tj * 64 + j) * 32 + ch * 16 + c4i];
                Bs[(c4i * 4 + 0) * 64 + j] = v.x;
                Bs[(c4i * 4 + 1) * 64 + j] = v.y;
                Bs[(c4i * 4 + 2) * 64 + j] = v.z;
                Bs[(c4i * 4 + 3) * 64 + j] = v.w;
            }
            __syncthreads();

            // k stepped by 4: float4 A broadcasts + float4 B rows
            #pragma unroll 2
            for (int k4 = 0; k4 < 16; k4++) {
                float4 b0 = *(const float4*)&Bs[(4 * k4 + 0) * 64 + 4 * tx];
                float4 b1 = *(const float4*)&Bs[(4 * k4 + 1) * 64 + 4 * tx];
                float4 b2 = *(const float4*)&Bs[(4 * k4 + 2) * 64 + 4 * tx];
                float4 b3 = *(const float4*)&Bs[(4 * k4 + 3) * 64 + 4 * tx];
                #pragma unroll
                for (int q = 0; q < 4; q++) {
                    float4 a = *(const float4*)&As[(4 * ty + q) * 68 + 4 * k4];
                    acc[q][0] = fmaf(a.x, b0.x, acc[q][0]);
                    acc[q][1] = fmaf(a.x, b0.y, acc[q][1]);
                    acc[q][2] = fmaf(a.x, b0.z, acc[q][2]);
                    acc[q][3] = fmaf(a.x, b0.w, acc[q][3]);
                    acc[q][0] = fmaf(a.y, b1.x, acc[q][0]);
                    acc[q][1] = fmaf(a.y, b1.y, acc[q][1]);
                    acc[q][2] = fmaf(a.y, b1.z, acc[q][2]);
                    acc[q][3] = fmaf(a.y, b1.w, acc[q][3]);
                    acc[q][0] = fmaf(a.z, b2.x, acc[q][0]);
                    acc[q][1] = fmaf(a.z, b2.y, acc[q][1]);
                    acc[q][2] = fmaf(a.z, b2.z, acc[q][2]);
                    acc[q][3] = fmaf(a.z, b2.w, acc[q][3]);
                    acc[q][0] = fmaf(a.w, b3.x, acc[q][0]);
                    acc[q][1] = fmaf(a.w, b3.y, acc[q][1]);
                    acc[q][2] = fmaf(a.w, b3.z, acc[q][2]);
                    acc[q][3] = fmaf(a.w, b3.w, acc[q][3]);
                }
            }
        }
        #pragma unroll
        for (int q = 0; q < 4; q++) {
            int row = ti * 64 + 4 * ty + q;
            float4 o = make_float4(acc[q][0], acc[q][1], acc[q][2], acc[q][3]);
            *(float4*)&g_dot[(size_t)row * n + tj * 64 + 4 * tx] = o;
        }
    } else if (b < lab_block) {
        int r0 = (b - dist_blocks) * 32;
        #pragma unroll
        for (int it = 0; it < 4; it++) {
            int row = r0 + wid + it * 8;
            float4 v = e4[(size_t)row * 32 + lane];
            float s = v.x * v.x + v.y * v.y + v.z * v.z + v.w * v.w;
            #pragma unroll
            for (int off = 16; off; off >>= 1)
                s += __shfl_down_sync(0xFFFFFFFFu, s, off);
            if (lane == 0) g_sq[row] = s;
        }
    } else if (b == lab_block) {
        if (tid == 0) s_is64 = 1;
        __syncthreads();
        for (int idx = tid; idx < n / 2; idx += 256)
            if (lab32[2 * idx + 1] != 0) atomicExch(&s_is64, 0);
        __syncthreads();
        const bool is64 = (s_is64 != 0);
        for (int i2 = tid; i2 < n; i2 += 256)
            g_lab[i2] = is64 ? lab32[2 * i2] : lab32[i2];
    }

    // ================= grid barrier =================
    __threadfence();
    __syncthreads();
    if (tid == 0) {
        atomicAdd(&g_bar1, 1);
        volatile int* vb = &g_bar1;
        while (*vb < GRID) { __nanosleep(32); }
    }
    __syncthreads();

    // ================= phase 2: anchors via counting sort =================
    float lsum = 0.f;
    int   lcnt = 0;
    int   vtot = 0;

    for (int i = b; i < n; i += GRID) {
        const int   li  = g_lab[i];
        const float sqi = g_sq[i];
        const float* __restrict__ drow = &g_dot[(size_t)i * n];

        __syncthreads();
        hcnt[tid] = 0;
        __syncthreads();

        float dvs[3];
        int   typ[3];                    // 0 = neg, 1 = pos, 2 = skip
        #pragma unroll
        for (int s = 0; s < 3; s++) {
            int j = tid + s * 256;
            typ[s] = 2; dvs[s] = 0.f;
            if (j < n) {
                float dv = sqrtf(fmaxf(sqi + g_sq[j] - 2.0f * drow[j], 0.0f));
                dvs[s] = dv;
                if (g_lab[j] == li) {
                    typ[s] = (j == i) ? 2 : 1;
                } else {
                    typ[s] = 0;
                    int bb = min(255, (int)(dv * BSCALE));
                    atomicAdd(&hcnt[bb], 1);
                }
            }
        }
        __syncthreads();

        // exclusive scan of counts -> pcs, cursors
        int vcnt = hcnt[tid];
        int inc = vcnt;
        #pragma unroll
        for (int off = 1; off < 32; off <<= 1) {
            int t = __shfl_up_sync(0xFFFFFFFFu, inc, off);
            if (lane >= off) inc += t;
        }
        if (lane == 31) swi[wid] = inc;
        __syncthreads();
        if (tid < 8) {
            int o = 0;
            for (int k = 0; k < tid; k++) o += swi[k];
            swi2[tid] = o;
        }
        __syncthreads();
        int exc = inc - vcnt + swi2[wid];
        pcs[tid] = exc;
        cur[tid] = exc;
        if (tid == 255) pcs[256] = exc + vcnt;
        __syncthreads();

        // scatter negatives grouped by bucket
        #pragma unroll
        for (int s = 0; s < 3; s++) {
            if (typ[s] == 0) {
                int bb = min(255, (int)(dvs[s] * BSCALE));
                int slot = atomicAdd(&cur[bb], 1);
                bval[slot] = dvs[s];
            }
        }
        __syncthreads();

        // per-bucket value sums -> exclusive scan pvs
        float sv = 0.f;
        {
            int s0 = pcs[tid], s1 = pcs[tid + 1];
            for (int k = s0; k < s1; k++) sv += bval[k];
        }
        float fin = sv;
        #pragma unroll
        for (int off = 1; off < 32; off <<= 1) {
            float t = __shfl_up_sync(0xFFFFFFFFu, fin, off);
            if (lane >= off) fin += t;
        }
        if (lane == 31) swf[wid] = fin;
        __syncthreads();
        if (tid < 8) {
            float o = 0.f;
            for (int k = 0; k < tid; k++) o += swf[k];
            swf2[tid] = o;
        }
        __syncthreads();
        pvs[tid] = fin - sv + swf2[wid];
        __syncthreads();

        // positives: O(1) prefix lookup + boundary-bucket exact scan
        const int Ntot = pcs[256];
        #pragma unroll
        for (int s = 0; s < 3; s++) {
            if (typ[s] == 1) {
                float t = dvs[s] + MARGIN;
                int bb = min(255, (int)(t * BSCALE));
                int cnt = pcs[bb];
                float sm = pvs[bb];
                int e1 = pcs[bb + 1];
                for (int k = pcs[bb]; k < e1; k++) {
                    float vv = bval[k];
                    if (vv < t) { cnt++; sm += vv; }
                }
                lcnt += cnt;
                lsum += (float)cnt * t - sm;
            }
        }
        vtot += (n - 1 - Ntot) * Ntot;
    }

    // block reduce
    #pragma unroll
    for (int off = 16; off; off >>= 1) {
        lsum += __shfl_down_sync(0xFFFFFFFFu, lsum, off);
        lcnt += __shfl_down_sync(0xFFFFFFFFu, lcnt, off);
    }
    if (lane == 0) { wsum[wid] = lsum; wcnt[wid] = lcnt; }
    __syncthreads();
    if (tid == 0) {
        float s = 0.f; int c = 0;
        #pragma unroll
        for (int w = 0; w < 8; w++) { s += wsum[w]; c += wcnt[w]; }
        g_bsum[b] = s;
        g_bcnt[b] = c;
        g_bval[b] = vtot;
    }

    // ================= phase 3: last block finalizes =================
    __threadfence();
    __syncthreads();
    if (tid == 0) s_old = atomicAdd(&g_bar2, 1);
    __syncthreads();
    if (s_old == GRID - 1) {
        float s = 0.f; int c = 0, v = 0;
        for (int idx = tid; idx < GRID; idx += 256) {
            s += g_bsum[idx];
            c += g_bcnt[idx];
            v += g_bval[idx];
        }
        #pragma unroll
        for (int off = 16; off; off >>= 1) {
            s += __shfl_down_sync(0xFFFFFFFFu, s, off);
            c += __shfl_down_sync(0xFFFFFFFFu, c, off);
            v += __shfl_down_sync(0xFFFFFFFFu, v, off);
        }
        __shared__ float fs[8];
        __shared__ int   fc[8], fv[8];
        if (lane == 0) { fs[wid] = s; fc[wid] = c; fv[wid] = v; }
        __syncthreads();
        if (tid == 0) {
            float total = 0.f; int cnt = 0, val = 0;
            #pragma unroll
            for (int w = 0; w < 8; w++) { total += fs[w]; cnt += fc[w]; val += fv[w]; }
            float num_non   = (float)cnt;
            float num_valid = (float)val;
            out[0] = (cnt > 0) ? total / fmaxf(num_non, 1.0f) : 0.0f;
            out[1] = num_valid;
            out[2] = num_non;
            out[3] = num_non / (num_valid + 1e-16f);
            g_bar1 = 0;
            g_bar2 = 0;
            __threadfence();
        }
    }
}

extern "C" void kernel_launch(void* const* d_in, const int* in_sizes, int n_in,
                              void* d_out, int out_size) {
    const float* e   = (const float*)d_in[0];   // embeddings [8,80,128] fp32
    const int*   lab = (const int*)d_in[1];     // labels (int64 or int32 view)
    int n = in_sizes[1];                        // 640

    fused_triplet_kernel<<<GRID, 256>>>(e, lab, (float*)d_out, n);
}

// round 8
// speedup vs baseline: 1.0303x; 1.0303x over previous
#include <cuda_runtime.h>

#define MARGIN  1.9f
#define GRID    592              // 4 blocks/SM on 148 SMs, all wave-1 resident
#define NMAXE   1024
#define BIGF    3.0e38f

// Scratch (no allocation allowed)
__device__ float g_dot[640 * 640];   // full dot products
__device__ float g_sq[NMAXE];        // = diag(dot), written by diagonal tiles
__device__ int   g_lab[NMAXE];
__device__ float g_bsum[GRID];
__device__ int   g_bcnt[GRID];
__device__ int   g_bval[GRID];
__device__ int   g_bar1 = 0;
__device__ int   g_bar2 = 0;

// Fused kernel, grid=592:
//  phase 1: blocks 0..399 : 32x32 full-k dot tiles (2x2 micro); diagonal tiles
//                           also emit g_sq from their diagonal accumulators
//           block  400    : label normalization; 401..591 idle
//  grid barrier
//  phase 2: block b -> anchors i = b, b+592 (sync-free brute-force P x 3-neg loop)
//  phase 3: last block reduces partials -> out[4], resets barriers
__global__ void __launch_bounds__(256, 4)
fused_triplet_kernel(const float* __restrict__ e, const int* __restrict__ lab32,
                     float* __restrict__ out, int n) {
    __shared__ float As[32 * 132];   // A tile rows x k (padded stride), 16.9 KB
    __shared__ float Bs[128 * 32];   // B tile k-major, 16 KB
    __shared__ int   sp, s_old, s_is64;
    __shared__ float wsum[8];
    __shared__ int   wcnt[8];

    const int b    = blockIdx.x;
    const int tid  = threadIdx.x;
    const int lane = tid & 31;
    const int wid  = tid >> 5;
    const unsigned lmask_lt = (1u << lane) - 1u;
    const float4* e4 = (const float4*)e;   // 32 float4 per embedding row

    const int tiles_x     = n >> 5;                    // 20
    const int dist_blocks = tiles_x * tiles_x;         // 400
    const int lab_block   = dist_blocks;               // 400

    // ================= phase 1 =================
    if (b < dist_blocks) {
        const int ti = b / tiles_x;
        const int tj = b % tiles_x;
        const int tx = tid & 15;     // col pair index (cols 2tx, 2tx+1)
        const int ty = tid >> 4;     // row pair index (rows 2ty, 2ty+1)

        // Load A tile: 32 rows x 32 float4, coalesced; conflict-free stores.
        #pragma unroll
        for (int r = 0; r < 4; r++) {
            int lin = tid + r * 256;
            int row = lin >> 5;          // 0..31
            int c4  = lin & 31;          // 0..31
            float4 v = e4[(size_t)(ti * 32 + row) * 32 + c4];
            *(float4*)&As[row * 132 + c4 * 4] = v;
        }
        // Load B tile k-major: Bs[k][j], conflict-free stores (j lane-varying).
        #pragma unroll
        for (int r = 0; r < 4; r++) {
            int lin = tid + r * 256;
            int j   = lin & 31;
            int c4  = lin >> 5;
            float4 v = e4[(size_t)(tj * 32 + j) * 32 + c4];
            Bs[(c4 * 4 + 0) * 32 + j] = v.x;
            Bs[(c4 * 4 + 1) * 32 + j] = v.y;
            Bs[(c4 * 4 + 2) * 32 + j] = v.z;
            Bs[(c4 * 4 + 3) * 32 + j] = v.w;
        }
        __syncthreads();

        float acc00 = 0.f, acc01 = 0.f, acc10 = 0.f, acc11 = 0.f;
        #pragma unroll 4
        for (int k4 = 0; k4 < 32; k4++) {
            float4 a0 = *(const float4*)&As[(2 * ty + 0) * 132 + 4 * k4];
            float4 a1 = *(const float4*)&As[(2 * ty + 1) * 132 + 4 * k4];
            float2 b0 = *(const float2*)&Bs[(4 * k4 + 0) * 32 + 2 * tx];
            float2 b1 = *(const float2*)&Bs[(4 * k4 + 1) * 32 + 2 * tx];
            float2 b2 = *(const float2*)&Bs[(4 * k4 + 2) * 32 + 2 * tx];
            float2 b3 = *(const float2*)&Bs[(4 * k4 + 3) * 32 + 2 * tx];
            acc00 = fmaf(a0.x, b0.x, acc00);
            acc01 = fmaf(a0.x, b0.y, acc01);
            acc10 = fmaf(a1.x, b0.x, acc10);
            acc11 = fmaf(a1.x, b0.y, acc11);
            acc00 = fmaf(a0.y, b1.x, acc00);
            acc01 = fmaf(a0.y, b1.y, acc01);
            acc10 = fmaf(a1.y, b1.x, acc10);
            acc11 = fmaf(a1.y, b1.y, acc11);
            acc00 = fmaf(a0.z, b2.x, acc00);
            acc01 = fmaf(a0.z, b2.y, acc01);
            acc10 = fmaf(a1.z, b2.x, acc10);
            acc11 = fmaf(a1.z, b2.y, acc11);
            acc00 = fmaf(a0.w, b3.x, acc00);
            acc01 = fmaf(a0.w, b3.y, acc01);
            acc10 = fmaf(a1.w, b3.x, acc10);
            acc11 = fmaf(a1.w, b3.y, acc11);
        }
        const int row0 = ti * 32 + 2 * ty;
        const int col0 = tj * 32 + 2 * tx;
        *(float2*)&g_dot[(size_t)(row0 + 0) * n + col0] = make_float2(acc00, acc01);
        *(float2*)&g_dot[(size_t)(row0 + 1) * n + col0] = make_float2(acc10, acc11);
        if (ti == tj) {
            // diagonal of dot = squared norms (matches reference exactly)
            if (2 * ty     == 2 * tx    ) g_sq[row0]     = acc00;
            if (2 * ty     == 2 * tx + 1) g_sq[row0]     = acc01;
            if (2 * ty + 1 == 2 * tx    ) g_sq[row0 + 1] = acc10;
            if (2 * ty + 1 == 2 * tx + 1) g_sq[row0 + 1] = acc11;
        }
    } else if (b == lab_block) {
        if (tid == 0) s_is64 = 1;
        __syncthreads();
        for (int idx = tid; idx < n / 2; idx += 256)
            if (lab32[2 * idx + 1] != 0) atomicExch(&s_is64, 0);
        __syncthreads();
        const bool is64 = (s_is64 != 0);
        for (int i2 = tid; i2 < n; i2 += 256)
            g_lab[i2] = is64 ? lab32[2 * i2] : lab32[i2];
    }

    // ================= grid barrier =================
    __threadfence();
    __syncthreads();
    if (tid == 0) {
        atomicAdd(&g_bar1, 1);
        volatile int* vb = &g_bar1;
        while (*vb < GRID) { __nanosleep(32); }
    }
    __syncthreads();

    // ================= phase 2: anchors (sync-free brute force) =================
    float* pos_d = As;               // reuse smem
    float lsum = 0.f;
    int   lcnt = 0;
    int   vtot = 0;

    for (int i = b; i < n; i += GRID) {
        const int   li  = g_lab[i];
        const float sqi = g_sq[i];
        const float* __restrict__ drow = &g_dot[(size_t)i * n];

        float nk0 = BIGF, nk1 = BIGF, nk2 = BIGF;
        float pv0 = 0.f, pv1 = 0.f, pv2 = 0.f;
        bool  ip0 = false, ip1 = false, ip2 = false;
        {
            int j = tid;
            float dv = sqrtf(fmaxf(sqi + g_sq[j] - 2.0f * drow[j], 0.0f));
            bool same = (g_lab[j] == li);
            nk0 = same ? BIGF : dv;
            ip0 = same && (j != i);
            pv0 = dv + MARGIN;
        }
        {
            int j = tid + 256;
            float dv = sqrtf(fmaxf(sqi + g_sq[j] - 2.0f * drow[j], 0.0f));
            bool same = (g_lab[j] == li);
            nk1 = same ? BIGF : dv;
            ip1 = same && (j != i);
            pv1 = dv + MARGIN;
        }
        if (tid + 512 < n) {
            int j = tid + 512;
            float dv = sqrtf(fmaxf(sqi + g_sq[j] - 2.0f * drow[j], 0.0f));
            bool same = (g_lab[j] == li);
            nk2 = same ? BIGF : dv;
            ip2 = same && (j != i);
            pv2 = dv + MARGIN;
        }

        __syncthreads();                 // prev anchor's P-loop done with pos_d
        if (tid == 0) sp = 0;
        __syncthreads();

        // warp-aggregated append of positives (d + MARGIN)
        {
            unsigned m = __ballot_sync(0xFFFFFFFFu, ip0);
            if (m) {
                int base = 0;
                if (lane == 0) base = atomicAdd(&sp, __popc(m));
                base = __shfl_sync(0xFFFFFFFFu, base, 0);
                if (ip0) pos_d[base + __popc(m & lmask_lt)] = pv0;
            }
        }
        {
            unsigned m = __ballot_sync(0xFFFFFFFFu, ip1);
            if (m) {
                int base = 0;
                if (lane == 0) base = atomicAdd(&sp, __popc(m));
                base = __shfl_sync(0xFFFFFFFFu, base, 0);
                if (ip1) pos_d[base + __popc(m & lmask_lt)] = pv1;
            }
        }
        {
            unsigned m = __ballot_sync(0xFFFFFFFFu, ip2);
            if (m) {
                int base = 0;
                if (lane == 0) base = atomicAdd(&sp, __popc(m));
                base = __shfl_sync(0xFFFFFFFFu, base, 0);
                if (ip2) pos_d[base + __popc(m & lmask_lt)] = pv2;
            }
        }
        __syncthreads();
        const int P = sp;
        if (tid < 4) pos_d[P + tid] = -BIGF;   // sentinel pad for 4-wide loop
        __syncthreads();

        // independent accumulator chains per j-slot
        float s0 = 0.f, s1 = 0.f, s2 = 0.f;
        int   c0 = 0,   c1 = 0,   c2 = 0;
        for (int jj = 0; jj < P; jj += 4) {
            float4 t = *(const float4*)&pos_d[jj];   // broadcast LDS.128
            if (nk0 < t.x) { s0 += t.x - nk0; c0++; }
            if (nk1 < t.x) { s1 += t.x - nk1; c1++; }
            if (nk2 < t.x) { s2 += t.x - nk2; c2++; }
            if (nk0 < t.y) { s0 += t.y - nk0; c0++; }
            if (nk1 < t.y) { s1 += t.y - nk1; c1++; }
            if (nk2 < t.y) { s2 += t.y - nk2; c2++; }
            if (nk0 < t.z) { s0 += t.z - nk0; c0++; }
            if (nk1 < t.z) { s1 += t.z - nk1; c1++; }
            if (nk2 < t.z) { s2 += t.z - nk2; c2++; }
            if (nk0 < t.w) { s0 += t.w - nk0; c0++; }
            if (nk1 < t.w) { s1 += t.w - nk1; c1++; }
            if (nk2 < t.w) { s2 += t.w - nk2; c2++; }
        }
        lsum += s0 + s1 + s2;
        lcnt += c0 + c1 + c2;
        vtot += P * (n - 1 - P);
    }

    // block reduce
    #pragma unroll
    for (int off = 16; off; off >>= 1) {
        lsum += __shfl_down_sync(0xFFFFFFFFu, lsum, off);
        lcnt += __shfl_down_sync(0xFFFFFFFFu, lcnt, off);
    }
    if (lane == 0) { wsum[wid] = lsum; wcnt[wid] = lcnt; }
    __syncthreads();
    if (tid == 0) {
        float s = 0.f; int c = 0;
        #pragma unroll
        for (int w = 0; w < 8; w++) { s += wsum[w]; c += wcnt[w]; }
        g_bsum[b] = s;
        g_bcnt[b] = c;
        g_bval[b] = vtot;
    }

    // ================= phase 3: last block finalizes =================
    __threadfence();
    __syncthreads();
    if (tid == 0) s_old = atomicAdd(&g_bar2, 1);
    __syncthreads();
    if (s_old == GRID - 1) {
        float s = 0.f; int c = 0, v = 0;
        for (int idx = tid; idx < GRID; idx += 256) {
            s += g_bsum[idx];
            c += g_bcnt[idx];
            v += g_bval[idx];
        }
        #pragma unroll
        for (int off = 16; off; off >>= 1) {
            s += __shfl_down_sync(0xFFFFFFFFu, s, off);
            c += __shfl_down_sync(0xFFFFFFFFu, c, off);
            v += __shfl_down_sync(0xFFFFFFFFu, v, off);
        }
        __shared__ float fs[8];
        __shared__ int   fc[8], fv[8];
        if (lane == 0) { fs[wid] = s; fc[wid] = c; fv[wid] = v; }
        __syncthreads();
        if (tid == 0) {
            float total = 0.f; int cnt = 0, val = 0;
            #pragma unroll
            for (int w = 0; w < 8; w++) { total += fs[w]; cnt += fc[w]; val += fv[w]; }
            float num_non   = (float)cnt;
            float num_valid = (float)val;
            out[0] = (cnt > 0) ? total / fmaxf(num_non, 1.0f) : 0.0f;
            out[1] = num_valid;
            out[2] = num_non;
            out[3] = num_non / (num_valid + 1e-16f);
            g_bar1 = 0;
            g_bar2 = 0;
            __threadfence();
        }
    }
}

extern "C" void kernel_launch(void* const* d_in, const int* in_sizes, int n_in,
                              void* d_out, int out_size) {
    const float* e   = (const float*)d_in[0];   // embeddings [8,80,128] fp32
    const int*   lab = (const int*)d_in[1];     // labels (int64 or int32 view)
    int n = in_sizes[1];                        // 640

    fused_triplet_kernel<<<GRID, 256>>>(e, lab, (float*)d_out, n);
}

// round 9
// speedup vs baseline: 1.2424x; 1.2058x over previous
#include <cuda_runtime.h>

#define MARGIN  1.9f
#define GRID    592              // 4 blocks/SM on 148 SMs, all wave-1 resident
#define NMAXE   1024
#define BIGF    3.0e38f

// Scratch (no allocation allowed)
__device__ float g_dot[640 * 640];   // full dot products (mirror filled from upper tiles)
__device__ float g_sq[NMAXE];        // = diag(dot), written by diagonal tiles
__device__ int   g_lab[NMAXE];
__device__ float g_bsum[GRID];
__device__ int   g_bcnt[GRID];
__device__ int   g_bval[GRID];
__device__ int   g_bar1 = 0;
__device__ int   g_bar2 = 0;

// Fused kernel, grid=592:
//  phase 1: blocks 0..209 : UPPER-TRIANGLE 32x32 dot tiles (symmetry: dot is
//                           symmetric, so compute ti<=tj only; off-diag tiles
//                           mirror their result through an smem transpose).
//           block  210    : label normalization; 211..591 idle
//  grid barrier
//  phase 2: block b -> anchors i = b, b+592 (sync-free brute-force loop)
//  phase 3: last block reduces partials -> out[4], resets barriers
__global__ void __launch_bounds__(256, 4)
fused_triplet_kernel(const float* __restrict__ e, const int* __restrict__ lab32,
                     float* __restrict__ out, int n) {
    __shared__ float As[32 * 132];   // A tile rows x k (padded), 16.9 KB
    __shared__ float Bs[128 * 32];   // B tile k-major, 16 KB (reused as transpose buf)
    __shared__ int   sp, s_old, s_is64;
    __shared__ float wsum[8];
    __shared__ int   wcnt[8];

    const int b    = blockIdx.x;
    const int tid  = threadIdx.x;
    const int lane = tid & 31;
    const int wid  = tid >> 5;
    const unsigned lmask_lt = (1u << lane) - 1u;
    const float4* e4 = (const float4*)e;   // 32 float4 per embedding row

    const int tiles_x    = n >> 5;                      // 20
    const int tri_blocks = (tiles_x * (tiles_x + 1)) / 2;  // 210 upper tiles
    const int lab_block  = tri_blocks;                  // 210

    // ================= phase 1 =================
    if (b < tri_blocks) {
        // invert triangular index -> (ti, tj) with tj >= ti
        int ti = 0, rrem = b;
        #pragma unroll 1
        for (; ti < tiles_x; ti++) {
            int cnt = tiles_x - ti;
            if (rrem < cnt) break;
            rrem -= cnt;
        }
        const int tj = ti + rrem;

        const int tx = tid & 15;     // col pair (cols 2tx, 2tx+1)
        const int ty = tid >> 4;     // row pair (rows 2ty, 2ty+1)

        // Load A tile (rows ti*32..): coalesced LDG.128, row-major padded.
        #pragma unroll
        for (int r = 0; r < 4; r++) {
            int lin = tid + r * 256;
            int row = lin >> 5;
            int c4  = lin & 31;
            float4 v = e4[(size_t)(ti * 32 + row) * 32 + c4];
            *(float4*)&As[row * 132 + c4 * 4] = v;
        }
        // Load B tile (rows tj*32..) k-major: Bs[k][j].
        #pragma unroll
        for (int r = 0; r < 4; r++) {
            int lin = tid + r * 256;
            int j   = lin & 31;
            int c4  = lin >> 5;
            float4 v = e4[(size_t)(tj * 32 + j) * 32 + c4];
            Bs[(c4 * 4 + 0) * 32 + j] = v.x;
            Bs[(c4 * 4 + 1) * 32 + j] = v.y;
            Bs[(c4 * 4 + 2) * 32 + j] = v.z;
            Bs[(c4 * 4 + 3) * 32 + j] = v.w;
        }
        __syncthreads();

        float acc00 = 0.f, acc01 = 0.f, acc10 = 0.f, acc11 = 0.f;
        #pragma unroll 4
        for (int k4 = 0; k4 < 32; k4++) {
            float4 a0 = *(const float4*)&As[(2 * ty + 0) * 132 + 4 * k4];
            float4 a1 = *(const float4*)&As[(2 * ty + 1) * 132 + 4 * k4];
            float2 b0 = *(const float2*)&Bs[(4 * k4 + 0) * 32 + 2 * tx];
            float2 b1 = *(const float2*)&Bs[(4 * k4 + 1) * 32 + 2 * tx];
            float2 b2 = *(const float2*)&Bs[(4 * k4 + 2) * 32 + 2 * tx];
            float2 b3 = *(const float2*)&Bs[(4 * k4 + 3) * 32 + 2 * tx];
            acc00 = fmaf(a0.x, b0.x, acc00);
            acc01 = fmaf(a0.x, b0.y, acc01);
            acc10 = fmaf(a1.x, b0.x, acc10);
            acc11 = fmaf(a1.x, b0.y, acc11);
            acc00 = fmaf(a0.y, b1.x, acc00);
            acc01 = fmaf(a0.y, b1.y, acc01);
            acc10 = fmaf(a1.y, b1.x, acc10);
            acc11 = fmaf(a1.y, b1.y, acc11);
            acc00 = fmaf(a0.z, b2.x, acc00);
            acc01 = fmaf(a0.z, b2.y, acc01);
            acc10 = fmaf(a1.z, b2.x, acc10);
            acc11 = fmaf(a1.z, b2.y, acc11);
            acc00 = fmaf(a0.w, b3.x, acc00);
            acc01 = fmaf(a0.w, b3.y, acc01);
            acc10 = fmaf(a1.w, b3.x, acc10);
            acc11 = fmaf(a1.w, b3.y, acc11);
        }
        const int row0 = ti * 32 + 2 * ty;   // global row (A side)
        const int col0 = tj * 32 + 2 * tx;   // global col (B side)
        // direct store: dot[row][col]
        *(float2*)&g_dot[(size_t)(row0 + 0) * n + col0] = make_float2(acc00, acc01);
        *(float2*)&g_dot[(size_t)(row0 + 1) * n + col0] = make_float2(acc10, acc11);

        if (ti == tj) {
            // diagonal of dot = squared norms
            if (2 * ty     == 2 * tx    ) g_sq[row0]     = acc00;
            if (2 * ty     == 2 * tx + 1) g_sq[row0]     = acc01;
            if (2 * ty + 1 == 2 * tx    ) g_sq[row0 + 1] = acc10;
            if (2 * ty + 1 == 2 * tx + 1) g_sq[row0 + 1] = acc11;
        } else {
            // mirror store dot[col][row] via smem transpose (coalesced STG.128)
            float* Tr = Bs;                  // reuse: [32][33]
            __syncthreads();                 // all k-loop reads of Bs done
            Tr[(2 * tx + 0) * 33 + 2 * ty + 0] = acc00;
            Tr[(2 * tx + 1) * 33 + 2 * ty + 0] = acc01;
            Tr[(2 * tx + 0) * 33 + 2 * ty + 1] = acc10;
            Tr[(2 * tx + 1) * 33 + 2 * ty + 1] = acc11;
            __syncthreads();
            int trow = tid >> 3;             // 0..31 (local col -> mirror row)
            int tc4  = tid & 7;              // 0..7
            float4 mv;
            mv.x = Tr[trow * 33 + tc4 * 4 + 0];
            mv.y = Tr[trow * 33 + tc4 * 4 + 1];
            mv.z = Tr[trow * 33 + tc4 * 4 + 2];
            mv.w = Tr[trow * 33 + tc4 * 4 + 3];
            *(float4*)&g_dot[(size_t)(tj * 32 + trow) * n + ti * 32 + tc4 * 4] = mv;
        }
    } else if (b == lab_block) {
        if (tid == 0) s_is64 = 1;
        __syncthreads();
        for (int idx = tid; idx < n / 2; idx += 256)
            if (lab32[2 * idx + 1] != 0) atomicExch(&s_is64, 0);
        __syncthreads();
        const bool is64 = (s_is64 != 0);
        for (int i2 = tid; i2 < n; i2 += 256)
            g_lab[i2] = is64 ? lab32[2 * i2] : lab32[i2];
    }

    // ================= grid barrier =================
    __threadfence();
    __syncthreads();
    if (tid == 0) {
        atomicAdd(&g_bar1, 1);
        volatile int* vb = &g_bar1;
        while (*vb < GRID) { __nanosleep(32); }
    }
    __syncthreads();

    // ================= phase 2: anchors (sync-free brute force) =================
    float* pos_d = As;               // reuse smem
    float lsum = 0.f;
    int   lcnt = 0;
    int   vtot = 0;

    for (int i = b; i < n; i += GRID) {
        const int   li  = g_lab[i];
        const float sqi = g_sq[i];
        const float* __restrict__ drow = &g_dot[(size_t)i * n];

        float nk0 = BIGF, nk1 = BIGF, nk2 = BIGF;
        float pv0 = 0.f, pv1 = 0.f, pv2 = 0.f;
        bool  ip0 = false, ip1 = false, ip2 = false;
        {
            int j = tid;
            float dv = sqrtf(fmaxf(sqi + g_sq[j] - 2.0f * drow[j], 0.0f));
            bool same = (g_lab[j] == li);
            nk0 = same ? BIGF : dv;
            ip0 = same && (j != i);
            pv0 = dv + MARGIN;
        }
        {
            int j = tid + 256;
            float dv = sqrtf(fmaxf(sqi + g_sq[j] - 2.0f * drow[j], 0.0f));
            bool same = (g_lab[j] == li);
            nk1 = same ? BIGF : dv;
            ip1 = same && (j != i);
            pv1 = dv + MARGIN;
        }
        if (tid + 512 < n) {
            int j = tid + 512;
            float dv = sqrtf(fmaxf(sqi + g_sq[j] - 2.0f * drow[j], 0.0f));
            bool same = (g_lab[j] == li);
            nk2 = same ? BIGF : dv;
            ip2 = same && (j != i);
            pv2 = dv + MARGIN;
        }

        __syncthreads();                 // prev anchor's P-loop done with pos_d
        if (tid == 0) sp = 0;
        __syncthreads();

        // warp-aggregated append of positives (d + MARGIN)
        {
            unsigned m = __ballot_sync(0xFFFFFFFFu, ip0);
            if (m) {
                int base = 0;
                if (lane == 0) base = atomicAdd(&sp, __popc(m));
                base = __shfl_sync(0xFFFFFFFFu, base, 0);
                if (ip0) pos_d[base + __popc(m & lmask_lt)] = pv0;
            }
        }
        {
            unsigned m = __ballot_sync(0xFFFFFFFFu, ip1);
            if (m) {
                int base = 0;
                if (lane == 0) base = atomicAdd(&sp, __popc(m));
                base = __shfl_sync(0xFFFFFFFFu, base, 0);
                if (ip1) pos_d[base + __popc(m & lmask_lt)] = pv1;
            }
        }
        {
            unsigned m = __ballot_sync(0xFFFFFFFFu, ip2);
            if (m) {
                int base = 0;
                if (lane == 0) base = atomicAdd(&sp, __popc(m));
                base = __shfl_sync(0xFFFFFFFFu, base, 0);
                if (ip2) pos_d[base + __popc(m & lmask_lt)] = pv2;
            }
        }
        __syncthreads();
        const int P = sp;
        if (tid < 4) pos_d[P + tid] = -BIGF;   // sentinel pad for 4-wide loop
        __syncthreads();

        // independent accumulator chains per j-slot
        float s0 = 0.f, s1 = 0.f, s2 = 0.f;
        int   c0 = 0,   c1 = 0,   c2 = 0;
        for (int jj = 0; jj < P; jj += 4) {
            float4 t = *(const float4*)&pos_d[jj];   // broadcast LDS.128
            if (nk0 < t.x) { s0 += t.x - nk0; c0++; }
            if (nk1 < t.x) { s1 += t.x - nk1; c1++; }
            if (nk2 < t.x) { s2 += t.x - nk2; c2++; }
            if (nk0 < t.y) { s0 += t.y - nk0; c0++; }
            if (nk1 < t.y) { s1 += t.y - nk1; c1++; }
            if (nk2 < t.y) { s2 += t.y - nk2; c2++; }
            if (nk0 < t.z) { s0 += t.z - nk0; c0++; }
            if (nk1 < t.z) { s1 += t.z - nk1; c1++; }
            if (nk2 < t.z) { s2 += t.z - nk2; c2++; }
            if (nk0 < t.w) { s0 += t.w - nk0; c0++; }
            if (nk1 < t.w) { s1 += t.w - nk1; c1++; }
            if (nk2 < t.w) { s2 += t.w - nk2; c2++; }
        }
        lsum += s0 + s1 + s2;
        lcnt += c0 + c1 + c2;
        vtot += P * (n - 1 - P);
    }

    // block reduce
    #pragma unroll
    for (int off = 16; off; off >>= 1) {
        lsum += __shfl_down_sync(0xFFFFFFFFu, lsum, off);
        lcnt += __shfl_down_sync(0xFFFFFFFFu, lcnt, off);
    }
    if (lane == 0) { wsum[wid] = lsum; wcnt[wid] = lcnt; }
    __syncthreads();
    if (tid == 0) {
        float s = 0.f; int c = 0;
        #pragma unroll
        for (int w = 0; w < 8; w++) { s += wsum[w]; c += wcnt[w]; }
        g_bsum[b] = s;
        g_bcnt[b] = c;
        g_bval[b] = vtot;
    }

    // ================= phase 3: last block finalizes =================
    __threadfence();
    __syncthreads();
    if (tid == 0) s_old = atomicAdd(&g_bar2, 1);
    __syncthreads();
    if (s_old == GRID - 1) {
        float s = 0.f; int c = 0, v = 0;
        for (int idx = tid; idx < GRID; idx += 256) {
            s += g_bsum[idx];
            c += g_bcnt[idx];
            v += g_bval[idx];
        }
        #pragma unroll
        for (int off = 16; off; off >>= 1) {
            s += __shfl_down_sync(0xFFFFFFFFu, s, off);
            c += __shfl_down_sync(0xFFFFFFFFu, c, off);
            v += __shfl_down_sync(0xFFFFFFFFu, v, off);
        }
        __shared__ float fs[8];
        __shared__ int   fc[8], fv[8];
        if (lane == 0) { fs[wid] = s; fc[wid] = c; fv[wid] = v; }
        __syncthreads();
        if (tid == 0) {
            float total = 0.f; int cnt = 0, val = 0;
            #pragma unroll
            for (int w = 0; w < 8; w++) { total += fs[w]; cnt += fc[w]; val += fv[w]; }
            float num_non   = (float)cnt;
            float num_valid = (float)val;
            out[0] = (cnt > 0) ? total / fmaxf(num_non, 1.0f) : 0.0f;
            out[1] = num_valid;
            out[2] = num_non;
            out[3] = num_non / (num_valid + 1e-16f);
            g_bar1 = 0;
            g_bar2 = 0;
            __threadfence();
        }
    }
}

extern "C" void kernel_launch(void* const* d_in, const int* in_sizes, int n_in,
                              void* d_out, int out_size) {
    const float* e   = (const float*)d_in[0];   // embeddings [8,80,128] fp32
    const int*   lab = (const int*)d_in[1];     // labels (int64 or int32 view)
    int n = in_sizes[1];                        // 640

    fused_triplet_kernel<<<GRID, 256>>>(e, lab, (float*)d_out, n);
}